// round 1
// baseline (speedup 1.0000x reference)
#include <cuda_runtime.h>
#include <math_constants.h>

#define DIM 128
#define KCODES 2048
#define NROWS 65536
#define NZ (NROWS * DIM)
#define TILE_M 64
#define TILE_N 128
#define NTHREADS 256
#define NCHUNKS (KCODES / TILE_N)

__device__ float g_t[KCODES];     // ||e_j||^2 (fp32, sequential-k rounding)
__device__ int   g_idx[NROWS];    // argmin indices
__device__ float g_part[1024];    // per-block loss partials

// ---- f32x2 helpers (Blackwell packed fp32 pipe; ptxas never emits these from C++) ----
#define FMA2(d, a, b) asm("fma.rn.f32x2 %0, %1, %2, %0;" : "+l"(d) : "l"(a), "l"(b))

static __device__ __forceinline__ unsigned long long pack2(float x) {
    unsigned long long r;
    unsigned int u = __float_as_uint(x);
    asm("mov.b64 %0, {%1, %1};" : "=l"(r) : "r"(u));
    return r;
}
static __device__ __forceinline__ void unpack2(unsigned long long v, float& lo, float& hi) {
    unsigned int a, b;
    asm("mov.b64 {%0, %1}, %2;" : "=r"(a), "=r"(b) : "l"(v));
    lo = __uint_as_float(a);
    hi = __uint_as_float(b);
}

// ---- ||e_j||^2 ----
__global__ void k_embnorm(const float* __restrict__ emb) {
    int j = blockIdx.x * blockDim.x + threadIdx.x;
    if (j < KCODES) {
        const float* e = emb + (size_t)j * DIM;
        float s = 0.f;
        #pragma unroll 8
        for (int k = 0; k < DIM; ++k)
            s = __fadd_rn(s, __fmul_rn(e[k], e[k]));
        g_t[j] = s;
    }
}

// ---- fused distance-GEMM + argmin ----
// Block: 64 rows x all 2048 codes (16 chunks of 128). 256 threads: thread tile 4 rows x 8 codes.
// SMEM k-major; e tile group-swizzled by (k>>2) for conflict-free STS (coalesced copy) and LDS.128.
__global__ __launch_bounds__(NTHREADS, 2)
void k_argmin(const float* __restrict__ z, const float* __restrict__ emb) {
    extern __shared__ float sm[];
    float* zs = sm;                       // [128][64]   z tile, k-major
    float* es = zs + DIM * TILE_M;        // [128][128]  e chunk, k-major, swizzled
    float* ts = es + DIM * TILE_N;        // [128]       ||e||^2 for chunk
    float* ss = ts + TILE_N;              // [64]        ||z||^2 per row

    const int tid = threadIdx.x;
    const int rbase = blockIdx.x * TILE_M;

    // load z tile (transpose to k-major)
    for (int i = tid; i < TILE_M * (DIM / 4); i += NTHREADS) {
        int r  = i & (TILE_M - 1);
        int k4 = i >> 6;
        float4 v = *(const float4*)(z + (size_t)(rbase + r) * DIM + k4 * 4);
        zs[(k4 * 4 + 0) * TILE_M + r] = v.x;
        zs[(k4 * 4 + 1) * TILE_M + r] = v.y;
        zs[(k4 * 4 + 2) * TILE_M + r] = v.z;
        zs[(k4 * 4 + 3) * TILE_M + r] = v.w;
    }
    __syncthreads();

    // row norms s_r = sum z^2 (fp32 sequential; uniform-ulp shifts commute with grid rounding)
    if (tid < TILE_M) {
        float s = 0.f;
        #pragma unroll 8
        for (int k = 0; k < DIM; ++k) {
            float v = zs[k * TILE_M + tid];
            s = __fadd_rn(s, __fmul_rn(v, v));
        }
        ss[tid] = s;
    }
    __syncthreads();

    const int tc = tid & 15;   // code-group: covers codes {4tc..4tc+3} U {64+4tc..64+4tc+3}
    const int tr = tid >> 4;   // row-group:  rows 4tr..4tr+3

    float s_r[4];
    #pragma unroll
    for (int r = 0; r < 4; ++r) s_r[r] = ss[tr * 4 + r];

    float best[4];
    int   bidx[4];
    #pragma unroll
    for (int r = 0; r < 4; ++r) { best[r] = CUDART_INF_F; bidx[r] = 0; }

    for (int ch = 0; ch < NCHUNKS; ++ch) {
        const int cbase = ch * TILE_N;
        __syncthreads();  // previous chunk's es/ts fully consumed

        // e chunk: coalesced gmem read (one warp per code row), swizzled STS (conflict-free)
        #pragma unroll
        for (int it = 0; it < TILE_N / 8; ++it) {
            int cl = it * 8 + (tid >> 5);
            int k4 = tid & 31;
            float4 v = *(const float4*)(emb + (size_t)(cbase + cl) * DIM + k4 * 4);
            int g = cl >> 2, off = cl & 3;
            #pragma unroll
            for (int j = 0; j < 4; ++j) {
                int k = k4 * 4 + j;
                es[k * TILE_N + (((g ^ (k >> 2)) << 2) | off)] = ((const float*)&v)[j];
            }
        }
        if (tid < TILE_N) ts[tid] = g_t[cbase + tid];
        __syncthreads();

        unsigned long long acc[16];
        #pragma unroll
        for (int i = 0; i < 16; ++i) acc[i] = 0ull;

        #pragma unroll 4
        for (int k = 0; k < DIM; ++k) {
            const float* ek = es + k * TILE_N;
            const int sw = k >> 2;  // constant within unroll-4 body
            ulonglong2 eA = *(const ulonglong2*)(ek + ((tc ^ sw) << 2));
            ulonglong2 eB = *(const ulonglong2*)(ek + (((tc + 16) ^ sw) << 2));
            float4 zv = *(const float4*)(zs + k * TILE_M + (tr << 2));
            unsigned long long z0 = pack2(zv.x), z1 = pack2(zv.y),
                               z2 = pack2(zv.z), z3 = pack2(zv.w);
            FMA2(acc[0],  z0, eA.x); FMA2(acc[1],  z0, eA.y);
            FMA2(acc[2],  z0, eB.x); FMA2(acc[3],  z0, eB.y);
            FMA2(acc[4],  z1, eA.x); FMA2(acc[5],  z1, eA.y);
            FMA2(acc[6],  z1, eB.x); FMA2(acc[7],  z1, eB.y);
            FMA2(acc[8],  z2, eA.x); FMA2(acc[9],  z2, eA.y);
            FMA2(acc[10], z2, eB.x); FMA2(acc[11], z2, eB.y);
            FMA2(acc[12], z3, eA.x); FMA2(acc[13], z3, eA.y);
            FMA2(acc[14], z3, eB.x); FMA2(acc[15], z3, eB.y);
        }

        // dist = fl(fl(s - 2m) + t), exactly matching reference rounding (2*m is exact)
        #pragma unroll
        for (int r = 0; r < 4; ++r) {
            #pragma unroll
            for (int p = 0; p < 4; ++p) {  // ascending code order within thread
                float mlo, mhi;
                unpack2(acc[r * 4 + p], mlo, mhi);
                int clocal = (p < 2) ? (tc * 4 + p * 2) : (64 + tc * 4 + (p - 2) * 2);
                float d0 = __fadd_rn(__fsub_rn(s_r[r], __fmul_rn(2.f, mlo)), ts[clocal]);
                float d1 = __fadd_rn(__fsub_rn(s_r[r], __fmul_rn(2.f, mhi)), ts[clocal + 1]);
                int c0 = cbase + clocal;
                if (d0 < best[r]) { best[r] = d0; bidx[r] = c0; }
                if (d1 < best[r]) { best[r] = d1; bidx[r] = c0 + 1; }
            }
        }
    }

    // cross-thread (tc-group, 16 lanes) reduction, tie -> lowest index
    #pragma unroll
    for (int r = 0; r < 4; ++r) {
        float v = best[r];
        int   ix = bidx[r];
        #pragma unroll
        for (int off = 8; off > 0; off >>= 1) {
            float v2 = __shfl_down_sync(0xffffffffu, v, off, 16);
            int   i2 = __shfl_down_sync(0xffffffffu, ix, off, 16);
            if (v2 < v || (v2 == v && i2 < ix)) { v = v2; ix = i2; }
        }
        if (tc == 0) g_idx[rbase + tr * 4 + r] = ix;
    }
}

// ---- gather + straight-through output + index output + loss partials ----
__global__ __launch_bounds__(256)
void k_out(const float* __restrict__ z, const float* __restrict__ emb,
           float* __restrict__ out, long long out_size) {
    __shared__ float red[256];
    const int tid = threadIdx.x;
    const long long row0 = (long long)blockIdx.x * 64;
    float lsum = 0.f;

    for (int i = tid; i < 64 * (DIM / 4); i += 256) {  // warp = one full row (coalesced)
        long long r  = row0 + (i >> 5);
        int       d4 = (i & 31) * 4;
        int idx = g_idx[r];
        float4 q  = *(const float4*)(emb + (size_t)idx * DIM + d4);
        long long gi = r * DIM + d4;
        float4 zz = *(const float4*)(z + gi);
        float4 o; float df;
        df = __fsub_rn(q.x, zz.x); o.x = __fadd_rn(zz.x, df); lsum += df * df;
        df = __fsub_rn(q.y, zz.y); o.y = __fadd_rn(zz.y, df); lsum += df * df;
        df = __fsub_rn(q.z, zz.z); o.z = __fadd_rn(zz.z, df); lsum += df * df;
        df = __fsub_rn(q.w, zz.w); o.w = __fadd_rn(zz.w, df); lsum += df * df;
        if (gi + 3 < out_size) *(float4*)(out + gi) = o;
    }

    if (tid < 64) {
        long long r  = row0 + tid;
        long long gi = (long long)NZ + r;
        if (gi < out_size) out[gi] = (float)g_idx[r];
    }

    red[tid] = lsum;
    __syncthreads();
    for (int s = 128; s > 0; s >>= 1) {
        if (tid < s) red[tid] += red[tid + s];
        __syncthreads();
    }
    if (tid == 0) g_part[blockIdx.x] = red[0];
}

// ---- deterministic final loss reduce ----
__global__ void k_final(float* __restrict__ out, long long out_size) {
    __shared__ float red[256];
    const int tid = threadIdx.x;
    float s = 0.f;
    for (int i = tid; i < 1024; i += 256) s += g_part[i];  // fixed order
    red[tid] = s;
    __syncthreads();
    for (int w = 128; w > 0; w >>= 1) {
        if (tid < w) red[tid] += red[tid + w];
        __syncthreads();
    }
    if (tid == 0) {
        float m = red[0] / (float)NZ;
        float loss = __fadd_rn(m, __fmul_rn(0.25f, m));  // mean + beta*mean, beta=0.25
        long long li = (long long)NZ + NROWS;
        if (li < out_size) out[li] = loss;
    }
}

extern "C" void kernel_launch(void* const* d_in, const int* in_sizes, int n_in,
                              void* d_out, int out_size) {
    const float* z   = (const float*)d_in[0];
    const float* emb = (const float*)d_in[1];
    float* out = (float*)d_out;

    const int smem_bytes = (DIM * TILE_M + DIM * TILE_N + TILE_N + TILE_M) * (int)sizeof(float);
    cudaFuncSetAttribute(k_argmin, cudaFuncAttributeMaxDynamicSharedMemorySize, smem_bytes);

    k_embnorm<<<(KCODES + 255) / 256, 256>>>(emb);
    k_argmin<<<NROWS / TILE_M, NTHREADS, smem_bytes>>>(z, emb);
    k_out<<<NROWS / 64, 256>>>(z, emb, out, (long long)out_size);
    k_final<<<1, 256>>>(out, (long long)out_size);
}

// round 2
// speedup vs baseline: 1.1379x; 1.1379x over previous
#include <cuda_runtime.h>
#include <math_constants.h>

#define DIM 128
#define KCODES 2048
#define NROWS 65536
#define NZ (NROWS * DIM)
#define TILE_M 64
#define TILE_N 128
#define NTHREADS 128
#define NCHUNKS (KCODES / TILE_N)

__device__ __align__(16) float g_t[KCODES];     // ||e_j||^2
__device__ int   g_idx[NROWS];
__device__ float g_part[1024];

// ---- f32x2 helpers ----
#define FMA2(d, a, b) asm("fma.rn.f32x2 %0, %1, %2, %0;" : "+l"(d) : "l"(a), "l"(b))

static __device__ __forceinline__ unsigned long long pack2(float x) {
    unsigned long long r;
    unsigned int u = __float_as_uint(x);
    asm("mov.b64 %0, {%1, %1};" : "=l"(r) : "r"(u));
    return r;
}
static __device__ __forceinline__ void unpack2(unsigned long long v, float& lo, float& hi) {
    unsigned int a, b;
    asm("mov.b64 {%0, %1}, %2;" : "=r"(a), "=r"(b) : "l"(v));
    lo = __uint_as_float(a);
    hi = __uint_as_float(b);
}

// ---- ||e_j||^2 ----
__global__ void k_embnorm(const float* __restrict__ emb) {
    int j = blockIdx.x * blockDim.x + threadIdx.x;
    if (j < KCODES) {
        const float* e = emb + (size_t)j * DIM;
        float s = 0.f;
        #pragma unroll 8
        for (int k = 0; k < DIM; ++k)
            s = __fadd_rn(s, __fmul_rn(e[k], e[k]));
        g_t[j] = s;
    }
}

// ---- fused distance-GEMM + argmin ----
// Block: 64 rows x 2048 codes (16 chunks of 128). 128 threads: thread tile 8 rows x 8 codes.
__global__ __launch_bounds__(NTHREADS, 2)
void k_argmin(const float* __restrict__ z, const float* __restrict__ emb) {
    extern __shared__ float sm[];
    float* zs   = sm;                        // [128][64]   z tile, k-major   (32 KB)
    float* es   = zs + DIM * TILE_M;         // [128][128]  e chunk, k-major, swizzled (64 KB)
    float* tall = es + DIM * TILE_N;         // [2048]      full ||e||^2 table (8 KB)
    float* ss   = tall + KCODES;             // [64]        ||z||^2 per row

    const int tid = threadIdx.x;
    const int rbase = blockIdx.x * TILE_M;

    // stage full ||e||^2 table once
    for (int i = tid; i < KCODES / 4; i += NTHREADS)
        ((float4*)tall)[i] = ((const float4*)g_t)[i];

    // load z tile (transpose to k-major)
    for (int i = tid; i < TILE_M * (DIM / 4); i += NTHREADS) {
        int r  = i & (TILE_M - 1);
        int k4 = i >> 6;
        float4 v = *(const float4*)(z + (size_t)(rbase + r) * DIM + k4 * 4);
        zs[(k4 * 4 + 0) * TILE_M + r] = v.x;
        zs[(k4 * 4 + 1) * TILE_M + r] = v.y;
        zs[(k4 * 4 + 2) * TILE_M + r] = v.z;
        zs[(k4 * 4 + 3) * TILE_M + r] = v.w;
    }
    __syncthreads();

    // row norms (fp32 sequential k)
    if (tid < TILE_M) {
        float s = 0.f;
        #pragma unroll 8
        for (int k = 0; k < DIM; ++k) {
            float v = zs[k * TILE_M + tid];
            s = __fadd_rn(s, __fmul_rn(v, v));
        }
        ss[tid] = s;
    }
    __syncthreads();

    const int tc = tid & 15;   // code group: {4tc..4tc+3} U {64+4tc..64+4tc+3}
    const int tr = tid >> 4;   // row group:  rows 8tr..8tr+7

    float s_r[8];
    #pragma unroll
    for (int r = 0; r < 8; ++r) s_r[r] = ss[tr * 8 + r];

    float best[8];
    int   bidx[8];
    #pragma unroll
    for (int r = 0; r < 8; ++r) { best[r] = CUDART_INF_F; bidx[r] = 0; }

    for (int ch = 0; ch < NCHUNKS; ++ch) {
        const int cbase = ch * TILE_N;
        __syncthreads();  // previous chunk's es fully consumed

        // e chunk: coalesced gmem read, swizzled STS
        #pragma unroll 4
        for (int it = 0; it < TILE_N / 4; ++it) {
            int cl = it * 4 + (tid >> 5);
            int k4 = tid & 31;
            float4 v = *(const float4*)(emb + (size_t)(cbase + cl) * DIM + k4 * 4);
            int g = cl >> 2, off = cl & 3;
            #pragma unroll
            for (int j = 0; j < 4; ++j) {
                int k = k4 * 4 + j;
                es[k * TILE_N + (((g ^ (k >> 2)) << 2) | off)] = ((const float*)&v)[j];
            }
        }
        __syncthreads();

        unsigned long long acc[32];
        #pragma unroll
        for (int i = 0; i < 32; ++i) acc[i] = 0ull;

        #pragma unroll 4
        for (int k = 0; k < DIM; ++k) {
            const float* ek = es + k * TILE_N;
            const int sw = k >> 2;  // constant within unroll-4 body
            ulonglong2 eA = *(const ulonglong2*)(ek + ((tc ^ sw) << 2));
            ulonglong2 eB = *(const ulonglong2*)(ek + (((tc + 16) ^ sw) << 2));
            const float* zk = zs + k * TILE_M + tr * 8;
            float4 za = *(const float4*)(zk);
            float4 zb = *(const float4*)(zk + 4);
            unsigned long long zp[8];
            zp[0] = pack2(za.x); zp[1] = pack2(za.y);
            zp[2] = pack2(za.z); zp[3] = pack2(za.w);
            zp[4] = pack2(zb.x); zp[5] = pack2(zb.y);
            zp[6] = pack2(zb.z); zp[7] = pack2(zb.w);
            #pragma unroll
            for (int r = 0; r < 8; ++r) {
                FMA2(acc[r * 4 + 0], zp[r], eA.x);
                FMA2(acc[r * 4 + 1], zp[r], eA.y);
                FMA2(acc[r * 4 + 2], zp[r], eB.x);
                FMA2(acc[r * 4 + 3], zp[r], eB.y);
            }
        }

        // dist = fl(fl(s - 2m) + t), identical rounding chain to reference
        #pragma unroll
        for (int r = 0; r < 8; ++r) {
            #pragma unroll
            for (int p = 0; p < 4; ++p) {  // ascending code order within thread
                float mlo, mhi;
                unpack2(acc[r * 4 + p], mlo, mhi);
                int clocal = (p < 2) ? (tc * 4 + p * 2) : (64 + tc * 4 + (p - 2) * 2);
                int c0 = cbase + clocal;
                float d0 = __fadd_rn(__fsub_rn(s_r[r], __fmul_rn(2.f, mlo)), tall[c0]);
                float d1 = __fadd_rn(__fsub_rn(s_r[r], __fmul_rn(2.f, mhi)), tall[c0 + 1]);
                if (d0 < best[r]) { best[r] = d0; bidx[r] = c0; }
                if (d1 < best[r]) { best[r] = d1; bidx[r] = c0 + 1; }
            }
        }
    }

    // cross-thread (16-lane tc group) reduction, tie -> lowest index
    #pragma unroll
    for (int r = 0; r < 8; ++r) {
        float v = best[r];
        int   ix = bidx[r];
        #pragma unroll
        for (int off = 8; off > 0; off >>= 1) {
            float v2 = __shfl_down_sync(0xffffffffu, v, off, 16);
            int   i2 = __shfl_down_sync(0xffffffffu, ix, off, 16);
            if (v2 < v || (v2 == v && i2 < ix)) { v = v2; ix = i2; }
        }
        if (tc == 0) g_idx[rbase + tr * 8 + r] = ix;
    }
}

// ---- gather + straight-through + indices + loss partials ----
__global__ __launch_bounds__(256)
void k_out(const float* __restrict__ z, const float* __restrict__ emb,
           float* __restrict__ out, long long out_size) {
    __shared__ float red[256];
    const int tid = threadIdx.x;
    const long long row0 = (long long)blockIdx.x * 64;
    float lsum = 0.f;

    for (int i = tid; i < 64 * (DIM / 4); i += 256) {
        long long r  = row0 + (i >> 5);
        int       d4 = (i & 31) * 4;
        int idx = g_idx[r];
        float4 q  = *(const float4*)(emb + (size_t)idx * DIM + d4);
        long long gi = r * DIM + d4;
        float4 zz = *(const float4*)(z + gi);
        float4 o; float df;
        df = __fsub_rn(q.x, zz.x); o.x = __fadd_rn(zz.x, df); lsum += df * df;
        df = __fsub_rn(q.y, zz.y); o.y = __fadd_rn(zz.y, df); lsum += df * df;
        df = __fsub_rn(q.z, zz.z); o.z = __fadd_rn(zz.z, df); lsum += df * df;
        df = __fsub_rn(q.w, zz.w); o.w = __fadd_rn(zz.w, df); lsum += df * df;
        if (gi + 3 < out_size) *(float4*)(out + gi) = o;
    }

    if (tid < 64) {
        long long r  = row0 + tid;
        long long gi = (long long)NZ + r;
        if (gi < out_size) out[gi] = (float)g_idx[r];
    }

    red[tid] = lsum;
    __syncthreads();
    for (int s = 128; s > 0; s >>= 1) {
        if (tid < s) red[tid] += red[tid + s];
        __syncthreads();
    }
    if (tid == 0) g_part[blockIdx.x] = red[0];
}

// ---- deterministic final loss reduce ----
__global__ void k_final(float* __restrict__ out, long long out_size) {
    __shared__ float red[256];
    const int tid = threadIdx.x;
    float s = 0.f;
    for (int i = tid; i < 1024; i += 256) s += g_part[i];
    red[tid] = s;
    __syncthreads();
    for (int w = 128; w > 0; w >>= 1) {
        if (tid < w) red[tid] += red[tid + w];
        __syncthreads();
    }
    if (tid == 0) {
        float m = red[0] / (float)NZ;
        float loss = __fadd_rn(m, __fmul_rn(0.25f, m));
        long long li = (long long)NZ + NROWS;
        if (li < out_size) out[li] = loss;
    }
}

extern "C" void kernel_launch(void* const* d_in, const int* in_sizes, int n_in,
                              void* d_out, int out_size) {
    const float* z   = (const float*)d_in[0];
    const float* emb = (const float*)d_in[1];
    float* out = (float*)d_out;

    const int smem_bytes = (DIM * TILE_M + DIM * TILE_N + KCODES + TILE_M) * (int)sizeof(float);
    cudaFuncSetAttribute(k_argmin, cudaFuncAttributeMaxDynamicSharedMemorySize, smem_bytes);

    k_embnorm<<<(KCODES + 255) / 256, 256>>>(emb);
    k_argmin<<<NROWS / TILE_M, NTHREADS, smem_bytes>>>(z, emb);
    k_out<<<NROWS / 64, 256>>>(z, emb, out, (long long)out_size);
    k_final<<<1, 256>>>(out, (long long)out_size);
}